// round 4
// baseline (speedup 1.0000x reference)
#include <cuda_runtime.h>
#include <cuda_bf16.h>
#include <cstdint>

#define NN 65536
#define NE 524288
#define HH 256
#define H4 64

// ------------------------- scratch (device globals; no allocs) -------------
__device__ float g_h   [NN*HH];
__device__ float g_h1  [NN*HH];
__device__ float g_h2  [NN*HH];
__device__ float g_skip[NN*HH];
__device__ float g_pre [NN*HH];
__device__ __nv_bfloat16 g_hh[NN*HH];   // h bf16 hi/lo
__device__ __nv_bfloat16 g_hl[NN*HH];
__device__ __nv_bfloat16 g_ah[NN*HH];   // agg bf16 hi/lo
__device__ __nv_bfloat16 g_al[NN*HH];
__device__ __nv_bfloat16 g_sh[NN*HH];   // skip bf16 hi/lo
__device__ __nv_bfloat16 g_sl[NN*HH];
__device__ __nv_bfloat16 g_wh[8*HH*HH]; // weights bf16 hi/lo
__device__ __nv_bfloat16 g_wl[8*HH*HH];
__device__ int   g_deg [NN];
__device__ float g_dinv[NN];
__device__ int   g_off [NN+1];
__device__ int   g_cur [NN];
__device__ int   g_csr [NE];
__device__ int   g_cnt [NN*3];
__device__ int   g_bsum[256];
__device__ float g_ps  [256*HH];
__device__ float g_pq  [256*HH];
__device__ float g_scale[HH];
__device__ float g_shift[HH];

// ------------------------- helpers ------------------------------------------
__device__ __forceinline__ uint32_t smem_u32(const void* p) {
    uint32_t a;
    asm("{ .reg .u64 t; cvta.to.shared.u64 t, %1; cvt.u32.u64 %0, t; }" : "=r"(a) : "l"(p));
    return a;
}

__device__ __forceinline__ void split4(float4 v, uint2& hi, uint2& lo) {
    __nv_bfloat16 hx = __float2bfloat16_rn(v.x);
    __nv_bfloat16 hy = __float2bfloat16_rn(v.y);
    __nv_bfloat16 hz = __float2bfloat16_rn(v.z);
    __nv_bfloat16 hw = __float2bfloat16_rn(v.w);
    float rx = v.x - __bfloat162float(hx);
    float ry = v.y - __bfloat162float(hy);
    float rz = v.z - __bfloat162float(hz);
    float rw = v.w - __bfloat162float(hw);
    __nv_bfloat16 lx = __float2bfloat16_rn(rx);
    __nv_bfloat16 ly = __float2bfloat16_rn(ry);
    __nv_bfloat16 lz = __float2bfloat16_rn(rz);
    __nv_bfloat16 lw = __float2bfloat16_rn(rw);
    hi.x = (uint32_t)__bfloat16_as_ushort(hx) | ((uint32_t)__bfloat16_as_ushort(hy) << 16);
    hi.y = (uint32_t)__bfloat16_as_ushort(hz) | ((uint32_t)__bfloat16_as_ushort(hw) << 16);
    lo.x = (uint32_t)__bfloat16_as_ushort(lx) | ((uint32_t)__bfloat16_as_ushort(ly) << 16);
    lo.y = (uint32_t)__bfloat16_as_ushort(lz) | ((uint32_t)__bfloat16_as_ushort(lw) << 16);
}

#define LDM4(r, addr) \
    asm volatile("ldmatrix.sync.aligned.m8n8.x4.shared.b16 {%0,%1,%2,%3}, [%4];" \
        : "=r"((r)[0]), "=r"((r)[1]), "=r"((r)[2]), "=r"((r)[3]) : "r"(addr))

#define MMA(c, a, b0, b1) \
    asm volatile("mma.sync.aligned.m16n8k16.row.col.f32.bf16.bf16.f32 " \
        "{%0,%1,%2,%3}, {%4,%5,%6,%7}, {%8,%9}, {%0,%1,%2,%3};" \
        : "+f"((c)[0]), "+f"((c)[1]), "+f"((c)[2]), "+f"((c)[3]) \
        : "r"((a)[0]), "r"((a)[1]), "r"((a)[2]), "r"((a)[3]), "r"(b0), "r"(b1))

#define CPASYNC(dst, src) \
    asm volatile("cp.async.cg.shared.global [%0], [%1], 16;" :: "r"(dst), "l"(src) : "memory")
#define CPCOMMIT() asm volatile("cp.async.commit_group;" ::: "memory")
#define CPWAIT0()  asm volatile("cp.async.wait_group 0;" ::: "memory")

// ------------------------- graph prep kernels -------------------------------
__global__ void k_zero() {
    int i = blockIdx.x * blockDim.x + threadIdx.x;
    if (i < NN) {
        g_deg[i] = 0; g_cur[i] = 0;
        g_cnt[3*i] = 0; g_cnt[3*i+1] = 0; g_cnt[3*i+2] = 0;
    }
}

__global__ void k_hist(const int* __restrict__ row, const int* __restrict__ col,
                       const int* __restrict__ ea) {
    int e = blockIdx.x * blockDim.x + threadIdx.x;
    if (e < NE) {
        atomicAdd(&g_deg[col[e]], 1);
        atomicAdd(&g_cnt[row[e]*3 + ea[e]], 1);
    }
}

__global__ void k_scanA() {
    __shared__ int s[256];
    int b = blockIdx.x, t = threadIdx.x;
    int i = b * 256 + t;
    int v = g_deg[i];
    s[t] = v;
    __syncthreads();
    for (int d = 1; d < 256; d <<= 1) {
        int x = (t >= d) ? s[t-d] : 0;
        __syncthreads();
        s[t] += x;
        __syncthreads();
    }
    g_off[i] = s[t] - v;
    if (t == 255) g_bsum[b] = s[255];
}

__global__ void k_scanB() {
    __shared__ int s[256];
    int t = threadIdx.x;
    int v = g_bsum[t];
    s[t] = v;
    __syncthreads();
    for (int d = 1; d < 256; d <<= 1) {
        int x = (t >= d) ? s[t-d] : 0;
        __syncthreads();
        s[t] += x;
        __syncthreads();
    }
    g_bsum[t] = s[t] - v;
}

__global__ void k_scanC() {
    int i = blockIdx.x * blockDim.x + threadIdx.x;
    if (i < NN) {
        g_off[i] += g_bsum[i >> 8];
        g_dinv[i] = 1.0f / (float)max(g_deg[i], 1);
        if (i == NN - 1) g_off[NN] = NE;
    }
}

__global__ void k_scatter(const int* __restrict__ row, const int* __restrict__ col) {
    int e = blockIdx.x * blockDim.x + threadIdx.x;
    if (e < NE) {
        int d = col[e];
        int p = g_off[d] + atomicAdd(&g_cur[d], 1);
        g_csr[p] = row[e];
    }
}

// weights -> bf16 hi/lo (8 matrices of 256x256)
__global__ void k_cvtw(const float* __restrict__ w0, const float* __restrict__ w1,
                       const float* __restrict__ w2, const float* __restrict__ w3,
                       const float* __restrict__ w4, const float* __restrict__ w5,
                       const float* __restrict__ w6, const float* __restrict__ w7) {
    int idx = blockIdx.x * blockDim.x + threadIdx.x;   // float4 index, 131072 total
    int m = idx >> 14;
    int off = idx & 16383;
    const float* src;
    switch (m) {
        case 0: src = w0; break; case 1: src = w1; break;
        case 2: src = w2; break; case 3: src = w3; break;
        case 4: src = w4; break; case 5: src = w5; break;
        case 6: src = w6; break; default: src = w7; break;
    }
    float4 v = ((const float4*)src)[off];
    uint2 hi, lo;
    split4(v, hi, lo);
    *(uint2*)(g_wh + (size_t)m * 65536 + off * 4) = hi;
    *(uint2*)(g_wl + (size_t)m * 65536 + off * 4) = lo;
}

// h[i] = emb_node[x[i]] + sum_a cnt[i][a]*emb_edge[a]; writes fp32 + bf16 split
__global__ void k_inith(const int* __restrict__ x, const float* __restrict__ en,
                        const float* __restrict__ ee) {
    int i = blockIdx.x;
    int t = threadIdx.x;   // 0..63
    int xi = x[i];
    float c0 = (float)g_cnt[3*i], c1 = (float)g_cnt[3*i+1], c2 = (float)g_cnt[3*i+2];
    const float4* en4 = (const float4*)en;
    const float4* ee4 = (const float4*)ee;
    float4 v  = en4[xi * H4 + t];
    float4 e0 = ee4[t], e1 = ee4[H4 + t], e2 = ee4[2*H4 + t];
    v.x += c0*e0.x + c1*e1.x + c2*e2.x;
    v.y += c0*e0.y + c1*e1.y + c2*e2.y;
    v.z += c0*e0.z + c1*e1.z + c2*e2.z;
    v.w += c0*e0.w + c1*e1.w + c2*e2.w;
    ((float4*)g_h)[i * H4 + t] = v;
    uint2 hi, lo;
    split4(v, hi, lo);
    *(uint2*)(g_hh + (size_t)i * HH + t * 4) = hi;
    *(uint2*)(g_hl + (size_t)i * HH + t * 4) = lo;
}

// mean-aggregate fp32 gather -> bf16 hi/lo output
__global__ void k_agg(const float* __restrict__ in,
                      __nv_bfloat16* __restrict__ oh, __nv_bfloat16* __restrict__ ol) {
    int w = threadIdx.x >> 5, lane = threadIdx.x & 31;
    int i = blockIdx.x * 8 + w;
    int s = g_off[i], e = g_off[i+1];
    const float4* in4 = (const float4*)in;
    float4 x0 = make_float4(0.f,0.f,0.f,0.f);
    float4 x1 = make_float4(0.f,0.f,0.f,0.f);
    for (int p = s; p < e; ++p) {
        int src = g_csr[p];
        float4 v0 = in4[src * H4 + lane];
        float4 v1 = in4[src * H4 + 32 + lane];
        x0.x += v0.x; x0.y += v0.y; x0.z += v0.z; x0.w += v0.w;
        x1.x += v1.x; x1.y += v1.y; x1.z += v1.z; x1.w += v1.w;
    }
    float di = g_dinv[i];
    x0.x *= di; x0.y *= di; x0.z *= di; x0.w *= di;
    x1.x *= di; x1.y *= di; x1.z *= di; x1.w *= di;
    uint2 hi, lo;
    split4(x0, hi, lo);
    *(uint2*)(oh + (size_t)i * HH + lane * 4) = hi;
    *(uint2*)(ol + (size_t)i * HH + lane * 4) = lo;
    split4(x1, hi, lo);
    *(uint2*)(oh + (size_t)i * HH + 128 + lane * 4) = hi;
    *(uint2*)(ol + (size_t)i * HH + 128 + lane * 4) = lo;
}

// ------------------------- tensor-core GEMM (pre-split bf16) ----------------
// C[128 x 256] = A1 @ W1^T [+ A2 @ W2^T] [+ bias] [+ add1] [+ add2]
// All GEMM operands pre-split to bf16 hi/lo. 3-product fp32 emulation.
#define PITCH 80
#define AH_O 0
#define AL_O 10240
#define BH_O 20480
#define BL_O 40960
#define STG  61440
#define SM_BYTES (2*STG)

__global__ __launch_bounds__(256, 1)
void k_mma(const __nv_bfloat16* __restrict__ A1h, const __nv_bfloat16* __restrict__ A1l,
           const __nv_bfloat16* __restrict__ A2h, const __nv_bfloat16* __restrict__ A2l,
           const __nv_bfloat16* __restrict__ W1h, const __nv_bfloat16* __restrict__ W1l,
           const __nv_bfloat16* __restrict__ W2h, const __nv_bfloat16* __restrict__ W2l,
           const float* __restrict__ bias,
           const float* __restrict__ add1, const float* __restrict__ add2,
           float* __restrict__ C,
           __nv_bfloat16* __restrict__ Cbh, __nv_bfloat16* __restrict__ Cbl,
           int dual)
{
    extern __shared__ char sb[];
    const uint32_t sa = smem_u32(sb);
    const int t = threadIdx.x, wid = t >> 5, lane = t & 31;
    const int wm = wid & 1, wn = wid >> 1;
    const int bm = blockIdx.x * 128;
    const int S = dual ? 16 : 8;

    auto issue = [&](int s) {
        const __nv_bfloat16* Ah = (s < 8) ? A1h : A2h;
        const __nv_bfloat16* Al = (s < 8) ? A1l : A2l;
        const __nv_bfloat16* Wh = (s < 8) ? W1h : W2h;
        const __nv_bfloat16* Wl = (s < 8) ? W1l : W2l;
        const int ko = (s & 7) * 32;
        const uint32_t bufa = sa + (s & 1) * STG;
#pragma unroll
        for (int q = 0; q < 2; q++) {
            int idx = q * 256 + t;
            int r = idx >> 2, c = idx & 3;
            uint32_t d = bufa + AH_O + r * PITCH + c * 16;
            CPASYNC(d, Ah + (size_t)(bm + r) * HH + ko + c * 8);
            CPASYNC(d + (AL_O - AH_O), Al + (size_t)(bm + r) * HH + ko + c * 8);
        }
#pragma unroll
        for (int q = 0; q < 4; q++) {
            int idx = q * 256 + t;
            int r = idx >> 2, c = idx & 3;
            uint32_t d = bufa + BH_O + r * PITCH + c * 16;
            CPASYNC(d, Wh + (size_t)r * HH + ko + c * 8);
            CPASYNC(d + (BL_O - BH_O), Wl + (size_t)r * HH + ko + c * 8);
        }
        CPCOMMIT();
    };

    float acc[4][8][4];
#pragma unroll
    for (int i = 0; i < 4; i++)
#pragma unroll
        for (int j = 0; j < 8; j++)
#pragma unroll
            for (int q = 0; q < 4; q++) acc[i][j][q] = 0.f;

    issue(0);

    for (int s = 0; s < S; s++) {
        CPWAIT0();
        __syncthreads();
        if (s + 1 < S) issue(s + 1);

        const uint32_t bufa = sa + (s & 1) * STG;
        const uint32_t aoff = bufa + AH_O
            + (uint32_t)(wm * 64 + (lane & 15)) * PITCH + ((lane >> 4) & 1) * 16;
        const uint32_t boff = bufa + BH_O
            + (uint32_t)(wn * 64 + (lane & 7) + ((lane >> 4) & 1) * 8) * PITCH
            + ((lane >> 3) & 1) * 16;

#pragma unroll
        for (int kk = 0; kk < 2; kk++) {
            uint32_t ah[4][4], al[4][4];
#pragma unroll
            for (int mi = 0; mi < 4; mi++) {
                uint32_t ad = aoff + mi * (16 * PITCH) + kk * 32;
                LDM4(ah[mi], ad);
                LDM4(al[mi], ad + (AL_O - AH_O));
            }
#pragma unroll
            for (int nb = 0; nb < 4; nb++) {
                uint32_t bh[4], bl[4];
                uint32_t bd = boff + nb * (16 * PITCH) + kk * 32;
                LDM4(bh, bd);
                LDM4(bl, bd + (BL_O - BH_O));
#pragma unroll
                for (int j2 = 0; j2 < 2; j2++) {
                    int nj = nb * 2 + j2;
                    uint32_t b0h = bh[j2*2], b1h = bh[j2*2+1];
                    uint32_t b0l = bl[j2*2], b1l = bl[j2*2+1];
#pragma unroll
                    for (int mi = 0; mi < 4; mi++) {
                        MMA(acc[mi][nj], ah[mi], b0h, b1h);
                        MMA(acc[mi][nj], ah[mi], b0l, b1l);
                        MMA(acc[mi][nj], al[mi], b0h, b1h);
                    }
                }
            }
        }
    }

    // ---- epilogue: direct stores with fused bias/adds ----
    const int g = lane >> 2, tig = lane & 3;
#pragma unroll
    for (int nj = 0; nj < 8; nj++) {
        int cc = wn * 64 + nj * 8 + tig * 2;
        float2 bv = make_float2(0.f, 0.f);
        if (bias) bv = *(const float2*)&bias[cc];
#pragma unroll
        for (int mi = 0; mi < 4; mi++) {
#pragma unroll
            for (int hr = 0; hr < 2; hr++) {
                int rr = bm + wm * 64 + mi * 16 + g + hr * 8;
                size_t base = (size_t)rr * HH + cc;
                float2 v = make_float2(acc[mi][nj][hr*2] + bv.x, acc[mi][nj][hr*2+1] + bv.y);
                if (add1) { float2 a = *(const float2*)&add1[base]; v.x += a.x; v.y += a.y; }
                if (add2) { float2 a = *(const float2*)&add2[base]; v.x += a.x; v.y += a.y; }
                *(float2*)&C[base] = v;
                if (Cbh) {
                    __nv_bfloat16 hx = __float2bfloat16_rn(v.x);
                    __nv_bfloat16 hy = __float2bfloat16_rn(v.y);
                    float lxf = v.x - __bfloat162float(hx);
                    float lyf = v.y - __bfloat162float(hy);
                    __nv_bfloat16 lx = __float2bfloat16_rn(lxf);
                    __nv_bfloat16 ly = __float2bfloat16_rn(lyf);
                    uint32_t hp = (uint32_t)__bfloat16_as_ushort(hx)
                                | ((uint32_t)__bfloat16_as_ushort(hy) << 16);
                    uint32_t lp = (uint32_t)__bfloat16_as_ushort(lx)
                                | ((uint32_t)__bfloat16_as_ushort(ly) << 16);
                    *(uint32_t*)(Cbh + base) = hp;
                    *(uint32_t*)(Cbl + base) = lp;
                }
            }
        }
    }
}

// ------------------------- BatchNorm ----------------------------------------
__global__ void k_bnstats() {
    int b = blockIdx.x, t = threadIdx.x;
    const float* p = g_pre + (long)b * 256 * HH + t;
    float s = 0.f, q = 0.f;
    for (int r = 0; r < 256; r++) {
        float v = p[(long)r * HH];
        s += v; q += v * v;
    }
    g_ps[b*HH + t] = s;
    g_pq[b*HH + t] = q;
}

__global__ void k_bnfinal(const float* __restrict__ g, const float* __restrict__ bb) {
    int t = threadIdx.x;
    float s = 0.f, q = 0.f;
    for (int b = 0; b < 256; b++) { s += g_ps[b*HH + t]; q += g_pq[b*HH + t]; }
    float m   = s * (1.0f / NN);
    float var = q * (1.0f / NN) - m * m;
    float sc  = g[t] * rsqrtf(var + 1e-5f);
    g_scale[t] = sc;
    g_shift[t] = bb[t] - m * sc;
}

__global__ void k_bnact(const float* __restrict__ a, float* __restrict__ out) {
    int i = blockIdx.x * blockDim.x + threadIdx.x;
    float al = __ldg(a);
    float4 v = ((const float4*)g_pre)[i];
    int c4 = i & (H4 - 1);
    float4 sc = ((const float4*)g_scale)[c4];
    float4 sh = ((const float4*)g_shift)[c4];
    v.x = v.x * sc.x + sh.x;  v.x = (v.x >= 0.f) ? v.x : al * v.x;
    v.y = v.y * sc.y + sh.y;  v.y = (v.y >= 0.f) ? v.y : al * v.y;
    v.z = v.z * sc.z + sh.z;  v.z = (v.z >= 0.f) ? v.z : al * v.z;
    v.w = v.w * sc.w + sh.w;  v.w = (v.w >= 0.f) ? v.w : al * v.w;
    ((float4*)out)[i] = v;
}

// ------------------------- host orchestration -------------------------------
template <typename T>
static void* symaddr_raw(T& sym) {
    void* p = nullptr;
    cudaGetSymbolAddress(&p, sym);
    return p;
}

extern "C" void kernel_launch(void* const* d_in, const int* in_sizes, int n_in,
                              void* d_out, int out_size)
{
    const int*   x   = (const int*)d_in[0];
    const int*   row = (const int*)d_in[1];
    const int*   col = row + NE;
    const int*   ea  = (const int*)d_in[2];
    const float* en  = (const float*)d_in[3];
    const float* ee  = (const float*)d_in[4];
    const float* Wl0 = (const float*)d_in[5];
    const float* bl0 = (const float*)d_in[6];
    const float* Wr0 = (const float*)d_in[7];
    const float* Wl1 = (const float*)d_in[8];
    const float* bl1 = (const float*)d_in[9];
    const float* Wr1 = (const float*)d_in[10];
    const float* Wl2 = (const float*)d_in[11];
    const float* bl2 = (const float*)d_in[12];
    const float* Wr2 = (const float*)d_in[13];
    const float* Wsk0= (const float*)d_in[14];
    const float* Wsk1= (const float*)d_in[15];
    const float* g0  = (const float*)d_in[16];
    const float* b0  = (const float*)d_in[17];
    const float* g1  = (const float*)d_in[18];
    const float* b1  = (const float*)d_in[19];
    const float* g2  = (const float*)d_in[20];
    const float* b2  = (const float*)d_in[21];
    const float* a0  = (const float*)d_in[22];
    const float* a1  = (const float*)d_in[23];
    const float* a2  = (const float*)d_in[24];

    float* h   = (float*)symaddr_raw(g_h);
    float* h1  = (float*)symaddr_raw(g_h1);
    float* h2  = (float*)symaddr_raw(g_h2);
    float* skp = (float*)symaddr_raw(g_skip);
    float* pre = (float*)symaddr_raw(g_pre);
    __nv_bfloat16* hh = (__nv_bfloat16*)symaddr_raw(g_hh);
    __nv_bfloat16* hl = (__nv_bfloat16*)symaddr_raw(g_hl);
    __nv_bfloat16* ah = (__nv_bfloat16*)symaddr_raw(g_ah);
    __nv_bfloat16* al = (__nv_bfloat16*)symaddr_raw(g_al);
    __nv_bfloat16* sh = (__nv_bfloat16*)symaddr_raw(g_sh);
    __nv_bfloat16* sl = (__nv_bfloat16*)symaddr_raw(g_sl);
    __nv_bfloat16* wh = (__nv_bfloat16*)symaddr_raw(g_wh);
    __nv_bfloat16* wl = (__nv_bfloat16*)symaddr_raw(g_wl);
    float* out = (float*)d_out;

    cudaFuncSetAttribute(k_mma, cudaFuncAttributeMaxDynamicSharedMemorySize, SM_BYTES);

    // weight slots: 0=Wl0 1=Wr0 2=Wl1 3=Wr1 4=Wl2 5=Wr2 6=Wsk0 7=Wsk1
    #define WH(i) (wh + (size_t)(i) * 65536)
    #define WL(i) (wl + (size_t)(i) * 65536)

    const int MG = NN / 128;   // 512 CTAs

    // --- graph preprocessing + conversions ---
    k_zero   <<<NN/256, 256>>>();
    k_hist   <<<NE/256, 256>>>(row, col, ea);
    k_cvtw   <<<512, 256>>>(Wl0, Wr0, Wl1, Wr1, Wl2, Wr2, Wsk0, Wsk1);
    k_scanA  <<<256, 256>>>();
    k_scanB  <<<1, 256>>>();
    k_scanC  <<<NN/256, 256>>>();
    k_scatter<<<NE/256, 256>>>(row, col);
    k_inith  <<<NN, 64>>>(x, en, ee);

    // --- layer 0 ---
    k_agg    <<<NN/8, 256>>>(h, ah, al);
    k_mma    <<<MG, 256, SM_BYTES>>>(ah, al, hh, hl, WH(0), WL(0), WH(1), WL(1),
                                     bl0, nullptr, nullptr, pre, nullptr, nullptr, 1);
    k_bnstats<<<256, 256>>>();
    k_bnfinal<<<1, 256>>>(g0, b0);
    k_bnact  <<<NN*H4/256, 256>>>(a0, h1);

    // --- layer 1 ---
    k_mma    <<<MG, 256, SM_BYTES>>>(hh, hl, nullptr, nullptr, WH(6), WL(6), nullptr, nullptr,
                                     nullptr, h1, nullptr, skp, sh, sl, 0);
    k_agg    <<<NN/8, 256>>>(skp, ah, al);
    k_mma    <<<MG, 256, SM_BYTES>>>(ah, al, sh, sl, WH(2), WL(2), WH(3), WL(3),
                                     bl1, nullptr, nullptr, pre, nullptr, nullptr, 1);
    k_bnstats<<<256, 256>>>();
    k_bnfinal<<<1, 256>>>(g1, b1);
    k_bnact  <<<NN*H4/256, 256>>>(a1, h2);

    // --- layer 2 ---
    k_mma    <<<MG, 256, SM_BYTES>>>(hh, hl, nullptr, nullptr, WH(7), WL(7), nullptr, nullptr,
                                     nullptr, h1, h2, skp, sh, sl, 0);
    k_agg    <<<NN/8, 256>>>(skp, ah, al);
    k_mma    <<<MG, 256, SM_BYTES>>>(ah, al, sh, sl, WH(4), WL(4), WH(5), WL(5),
                                     bl2, nullptr, nullptr, pre, nullptr, nullptr, 1);
    k_bnstats<<<256, 256>>>();
    k_bnfinal<<<1, 256>>>(g2, b2);
    k_bnact  <<<NN*H4/256, 256>>>(a2, out);
}